// round 1
// baseline (speedup 1.0000x reference)
#include <cuda_runtime.h>
#include <math.h>

#define BATCH 4
#define TT 2048
#define DD 512
#define HH 4
#define DKK 16
#define M_ROWS (BATCH*TT)     // 8192
#define NC 256                // q|k|v|g packed columns

// ---- scratch (device globals: no allocation allowed) ----
__device__ float g_Wcat[DD*NC];          // 512 KB
__device__ float g_qkvg[M_ROWS*NC];      // 8 MB
__device__ float g_a[M_ROWS*HH];         // 128 KB  (already -softplus'ed)
__device__ float g_bid[M_ROWS*HH];       // 128 KB
__device__ float g_z[M_ROWS*HH*DKK];     // 2 MB    (y * gate)

__device__ __forceinline__ float neg_inf() { return __int_as_float(0xff800000); }

// ---------------------------------------------------------------------------
// K0: pack Wq|Wk|Wv|Wg -> Wcat[512][256]
// ---------------------------------------------------------------------------
__global__ void pack_kernel(const float* __restrict__ Wq, const float* __restrict__ Wk,
                            const float* __restrict__ Wv, const float* __restrict__ Wg) {
    int idx = blockIdx.x * 256 + threadIdx.x;   // < 512*256
    int d = idx >> 8, c = idx & 255;
    float v;
    if      (c < 64)  v = Wq[d*64 + c];
    else if (c < 128) v = Wk[d*64 + (c-64)];
    else if (c < 192) v = Wv[d*64 + (c-128)];
    else              v = Wg[d*64 + (c-192)];
    g_Wcat[idx] = v;
}

// ---------------------------------------------------------------------------
// K1: qkvg = x @ Wcat   (M=8192, N=256, K=512), fp32 SGEMM 128x64x16
// ---------------------------------------------------------------------------
__global__ void __launch_bounds__(256) gemm_qkvg(const float* __restrict__ X) {
    const int BM = 128, BN = 64, BK = 16;
    __shared__ float As[BK][BM];
    __shared__ float Bs[BK][BN];

    int tid = threadIdx.x;
    int m0 = blockIdx.y * BM;
    int n0 = blockIdx.x * BN;
    int tm = (tid >> 4) * 8;   // 0..120
    int tn = (tid & 15) * 4;   // 0..60

    float acc[8][4];
    #pragma unroll
    for (int i = 0; i < 8; i++)
        #pragma unroll
        for (int j = 0; j < 4; j++) acc[i][j] = 0.f;

    for (int k0 = 0; k0 < DD; k0 += BK) {
        // A tile: 128x16 = 512 float4, 2 per thread
        #pragma unroll
        for (int i = 0; i < 2; i++) {
            int f = tid * 2 + i;
            int row = f >> 2, kq = (f & 3) * 4;
            float4 v = *(const float4*)&X[(size_t)(m0 + row) * DD + k0 + kq];
            As[kq+0][row] = v.x; As[kq+1][row] = v.y;
            As[kq+2][row] = v.z; As[kq+3][row] = v.w;
        }
        // B tile: 16x64 = 256 float4, 1 per thread
        {
            int krow = tid >> 4, c4 = (tid & 15) * 4;
            *(float4*)&Bs[krow][c4] = *(const float4*)&g_Wcat[(size_t)(k0 + krow) * NC + n0 + c4];
        }
        __syncthreads();
        #pragma unroll
        for (int kk = 0; kk < BK; kk++) {
            float4 a0 = *(const float4*)&As[kk][tm];
            float4 a1 = *(const float4*)&As[kk][tm + 4];
            float4 bv = *(const float4*)&Bs[kk][tn];
            float a[8] = {a0.x, a0.y, a0.z, a0.w, a1.x, a1.y, a1.z, a1.w};
            float b[4] = {bv.x, bv.y, bv.z, bv.w};
            #pragma unroll
            for (int i = 0; i < 8; i++)
                #pragma unroll
                for (int j = 0; j < 4; j++)
                    acc[i][j] += a[i] * b[j];
        }
        __syncthreads();
    }
    #pragma unroll
    for (int i = 0; i < 8; i++) {
        float4 o = make_float4(acc[i][0], acc[i][1], acc[i][2], acc[i][3]);
        *(float4*)&g_qkvg[(size_t)(m0 + tm + i) * NC + n0 + tn] = o;
    }
}

// ---------------------------------------------------------------------------
// K2: a = -softplus(x @ Wa + ba)   (one warp per row; 4 heads per warp)
// ---------------------------------------------------------------------------
__global__ void aproj_kernel(const float* __restrict__ X, const float* __restrict__ Wa,
                             const float* __restrict__ ba) {
    int gwarp = (blockIdx.x * blockDim.x + threadIdx.x) >> 5;   // row
    int lane  = threadIdx.x & 31;
    const float* xr = X + (size_t)gwarp * DD;
    float4 acc = make_float4(0.f, 0.f, 0.f, 0.f);
    #pragma unroll
    for (int i = 0; i < 16; i++) {
        int dd = i * 32 + lane;
        float xv = xr[dd];
        float4 w = *(const float4*)&Wa[dd * 4];
        acc.x += xv * w.x; acc.y += xv * w.y;
        acc.z += xv * w.z; acc.w += xv * w.w;
    }
    #pragma unroll
    for (int off = 16; off > 0; off >>= 1) {
        acc.x += __shfl_down_sync(0xffffffffu, acc.x, off);
        acc.y += __shfl_down_sync(0xffffffffu, acc.y, off);
        acc.z += __shfl_down_sync(0xffffffffu, acc.z, off);
        acc.w += __shfl_down_sync(0xffffffffu, acc.w, off);
    }
    if (lane == 0) {
        float zz[4] = {acc.x + ba[0], acc.y + ba[1], acc.z + ba[2], acc.w + ba[3]};
        #pragma unroll
        for (int h = 0; h < 4; h++) {
            float z = zz[h];
            float sp = fmaxf(z, 0.f) + log1pf(expf(-fabsf(z)));  // stable softplus
            g_a[gwarp * HH + h] = -sp;
        }
    }
}

// ---------------------------------------------------------------------------
// K3: bid = <q,k>/sqrt(DK)
// ---------------------------------------------------------------------------
__global__ void bid_kernel() {
    int idx = blockIdx.x * 256 + threadIdx.x;  // < 32768
    int row = idx >> 2, h = idx & 3;
    const float4* q = (const float4*)&g_qkvg[(size_t)row * NC + h * 16];
    const float4* k = (const float4*)&g_qkvg[(size_t)row * NC + 64 + h * 16];
    float s = 0.f;
    #pragma unroll
    for (int i = 0; i < 4; i++) {
        float4 a = q[i], b = k[i];
        s += a.x * b.x + a.y * b.y + a.z * b.z + a.w * b.w;
    }
    g_bid[idx] = s * 0.25f;   // 1/sqrt(16)
}

// ---------------------------------------------------------------------------
// K4: per-(b,h) prefix online-softmax scan + gate.  16 blocks x 256 threads,
//     8 timesteps per thread.  State = (m, d, n[16]); associative combine.
// ---------------------------------------------------------------------------
__global__ void __launch_bounds__(256) scan_kernel(const float* __restrict__ bg) {
    __shared__ float sp[2048];
    __shared__ float sscan[256];
    __shared__ float sm_[256];
    __shared__ float sd_[256];
    __shared__ float sn_[256 * 16];

    int t = threadIdx.x;
    int bh = blockIdx.x;
    int b = bh >> 2, h = bh & 3;
    int base = b * TT;
    int row0 = base + t * 8;

    // ---- Phase A: cumsum(a) -> p[time] = bid - cumA  (MU = 1) ----
    float la[8];
    {
        float run = 0.f;
        #pragma unroll
        for (int j = 0; j < 8; j++) { run += g_a[(size_t)(row0 + j) * HH + h]; la[j] = run; }
        sscan[t] = run;
    }
    __syncthreads();
    for (int off = 1; off < 256; off <<= 1) {
        float v = (t >= off) ? sscan[t - off] : 0.f;
        __syncthreads();
        sscan[t] += v;
        __syncthreads();
    }
    float exc = (t > 0) ? sscan[t - 1] : 0.f;
    #pragma unroll
    for (int j = 0; j < 8; j++)
        sp[t * 8 + j] = g_bid[(size_t)(row0 + j) * HH + h] - (exc + la[j]);
    __syncthreads();

    // ---- Phase B: local online-softmax state over 8 steps ----
    float m = neg_inf(), d = 0.f, n[16];
    #pragma unroll
    for (int i = 0; i < 16; i++) n[i] = 0.f;

    #pragma unroll
    for (int j = 0; j < 8; j++) {
        float pi = sp[t * 8 + j];
        const float4* vp = (const float4*)&g_qkvg[(size_t)(row0 + j) * NC + 128 + h * 16];
        float4 v0 = vp[0], v1 = vp[1], v2 = vp[2], v3 = vp[3];
        float vv[16] = {v0.x,v0.y,v0.z,v0.w, v1.x,v1.y,v1.z,v1.w,
                        v2.x,v2.y,v2.z,v2.w, v3.x,v3.y,v3.z,v3.w};
        if (pi > m) {
            float s = expf(m - pi);   // 0 when m = -inf
            #pragma unroll
            for (int i = 0; i < 16; i++) n[i] = n[i] * s + vv[i];
            d = d * s + 1.f;
            m = pi;
        } else {
            float w = expf(pi - m);
            #pragma unroll
            for (int i = 0; i < 16; i++) n[i] += w * vv[i];
            d += w;
        }
    }
    sm_[t] = m; sd_[t] = d;
    #pragma unroll
    for (int i = 0; i < 16; i++) sn_[t * 16 + i] = n[i];
    __syncthreads();

    // ---- Phase C: Hillis-Steele inclusive scan over 256 states ----
    for (int off = 1; off < 256; off <<= 1) {
        float lm = 0.f, ld = 0.f, ln[16];
        #pragma unroll
        for (int i = 0; i < 16; i++) ln[i] = 0.f;
        bool has = (t >= off);
        if (has) {
            lm = sm_[t - off]; ld = sd_[t - off];
            #pragma unroll
            for (int i = 0; i < 16; i++) ln[i] = sn_[(t - off) * 16 + i];
        }
        __syncthreads();
        if (has) {
            float M = fmaxf(lm, m);
            float sl = expf(lm - M), sr = expf(m - M);
            d = ld * sl + d * sr;
            #pragma unroll
            for (int i = 0; i < 16; i++) n[i] = ln[i] * sl + n[i] * sr;
            m = M;
            sm_[t] = m; sd_[t] = d;
            #pragma unroll
            for (int i = 0; i < 16; i++) sn_[t * 16 + i] = n[i];
        }
        __syncthreads();
    }

    // ---- exclusive prefix for this thread ----
    float em = neg_inf(), ed = 0.f, en[16];
    #pragma unroll
    for (int i = 0; i < 16; i++) en[i] = 0.f;
    if (t > 0) {
        em = sm_[t - 1]; ed = sd_[t - 1];
        #pragma unroll
        for (int i = 0; i < 16; i++) en[i] = sn_[(t - 1) * 16 + i];
    }

    // ---- Phase D: replay 8 steps, emit y = n/d, apply sigmoid gate ----
    m = em; d = ed;
    #pragma unroll
    for (int i = 0; i < 16; i++) n[i] = en[i];

    #pragma unroll
    for (int j = 0; j < 8; j++) {
        float pi = sp[t * 8 + j];
        const float4* vp = (const float4*)&g_qkvg[(size_t)(row0 + j) * NC + 128 + h * 16];
        float4 v0 = vp[0], v1 = vp[1], v2 = vp[2], v3 = vp[3];
        float vv[16] = {v0.x,v0.y,v0.z,v0.w, v1.x,v1.y,v1.z,v1.w,
                        v2.x,v2.y,v2.z,v2.w, v3.x,v3.y,v3.z,v3.w};
        if (pi > m) {
            float s = expf(m - pi);
            #pragma unroll
            for (int i = 0; i < 16; i++) n[i] = n[i] * s + vv[i];
            d = d * s + 1.f;
            m = pi;
        } else {
            float w = expf(pi - m);
            #pragma unroll
            for (int i = 0; i < 16; i++) n[i] += w * vv[i];
            d += w;
        }
        float inv = 1.f / d;

        const float4* gp = (const float4*)&g_qkvg[(size_t)(row0 + j) * NC + 192 + h * 16];
        float4 g0 = gp[0], g1 = gp[1], g2 = gp[2], g3 = gp[3];
        float gl[16] = {g0.x,g0.y,g0.z,g0.w, g1.x,g1.y,g1.z,g1.w,
                        g2.x,g2.y,g2.z,g2.w, g3.x,g3.y,g3.z,g3.w};
        float out[16];
        #pragma unroll
        for (int i = 0; i < 16; i++) {
            float gate = 1.f / (1.f + expf(-(gl[i] + bg[h * 16 + i])));
            out[i] = n[i] * inv * gate;
        }
        float* zp = &g_z[(size_t)(row0 + j) * 64 + h * 16];
        *(float4*)&zp[0]  = make_float4(out[0],  out[1],  out[2],  out[3]);
        *(float4*)&zp[4]  = make_float4(out[4],  out[5],  out[6],  out[7]);
        *(float4*)&zp[8]  = make_float4(out[8],  out[9],  out[10], out[11]);
        *(float4*)&zp[12] = make_float4(out[12], out[13], out[14], out[15]);
    }
}

// ---------------------------------------------------------------------------
// K5: out = z @ Wo   (M=8192, N=512, K=64), 32x128 tiles
// ---------------------------------------------------------------------------
__global__ void __launch_bounds__(256) out_gemm(const float* __restrict__ Wo,
                                                float* __restrict__ O) {
    __shared__ float Zs[32][64];
    __shared__ float Ws[64][128];
    int tid = threadIdx.x;
    int m0 = blockIdx.y * 32;
    int n0 = blockIdx.x * 128;

    #pragma unroll
    for (int i = 0; i < 2; i++) {
        int f = tid * 2 + i;            // < 512
        int row = f >> 4, c4 = (f & 15) * 4;
        *(float4*)&Zs[row][c4] = *(const float4*)&g_z[(size_t)(m0 + row) * 64 + c4];
    }
    #pragma unroll
    for (int i = 0; i < 8; i++) {
        int f = i * 256 + tid;          // < 2048
        int wr = f >> 5, c4 = (f & 31) * 4;
        *(float4*)&Ws[wr][c4] = *(const float4*)&Wo[(size_t)wr * 512 + n0 + c4];
    }
    __syncthreads();

    int tm = (tid >> 5) * 4;   // 0..28
    int tn = (tid & 31) * 4;   // 0..124
    float acc[4][4];
    #pragma unroll
    for (int i = 0; i < 4; i++)
        #pragma unroll
        for (int j = 0; j < 4; j++) acc[i][j] = 0.f;

    #pragma unroll
    for (int k = 0; k < 64; k++) {
        float a[4];
        #pragma unroll
        for (int i = 0; i < 4; i++) a[i] = Zs[tm + i][k];
        float4 bv = *(const float4*)&Ws[k][tn];
        float bvals[4] = {bv.x, bv.y, bv.z, bv.w};
        #pragma unroll
        for (int i = 0; i < 4; i++)
            #pragma unroll
            for (int j = 0; j < 4; j++)
                acc[i][j] += a[i] * bvals[j];
    }
    #pragma unroll
    for (int i = 0; i < 4; i++) {
        float4 o = make_float4(acc[i][0], acc[i][1], acc[i][2], acc[i][3]);
        *(float4*)&O[(size_t)(m0 + tm + i) * 512 + n0 + tn] = o;
    }
}

// ---------------------------------------------------------------------------
extern "C" void kernel_launch(void* const* d_in, const int* in_sizes, int n_in,
                              void* d_out, int out_size) {
    const float* x  = (const float*)d_in[0];
    const float* Wq = (const float*)d_in[1];
    const float* Wk = (const float*)d_in[2];
    const float* Wv = (const float*)d_in[3];
    const float* Wa = (const float*)d_in[4];
    const float* ba = (const float*)d_in[5];
    const float* Wg = (const float*)d_in[6];
    const float* bg = (const float*)d_in[7];
    const float* Wo = (const float*)d_in[8];
    float* out = (float*)d_out;

    pack_kernel<<<512, 256>>>(Wq, Wk, Wv, Wg);
    gemm_qkvg<<<dim3(NC / 64, M_ROWS / 128), 256>>>(x);
    aproj_kernel<<<M_ROWS / 8, 256>>>(x, Wa, ba);
    bid_kernel<<<(M_ROWS * HH) / 256, 256>>>();
    scan_kernel<<<BATCH * HH, 256>>>(bg);
    out_gemm<<<dim3(512 / 128, M_ROWS / 32), 256>>>(Wo, out);
}

// round 3
// speedup vs baseline: 1.0883x; 1.0883x over previous
#include <cuda_runtime.h>
#include <cuda_bf16.h>
#include <math.h>
#include <stdint.h>

#define BATCH 4
#define TT 2048
#define DD 512
#define HH 4
#define M_ROWS 8192
#define KQ 1536          // augmented K for qkvg GEMM
#define KO 192           // augmented K for out GEMM

// ---------------------------------------------------------------------------
// Global scratch (device globals; no allocation allowed)
// ---------------------------------------------------------------------------
__device__ uint4 g_xcat[1572864];   // 24MB  [8192][1536] bf16: x_hi | x_hi | x_lo
__device__ uint4 g_wcatT[49152];    // 1.5MB [256][1536] bf16: (W_hi|W_lo|W_hi)^T rows=n
__device__ uint4 g_zcat[196608];    // 3MB   [8192][192] bf16: z_hi | z_hi | z_lo
__device__ uint4 g_woT[12288];      // 384KB [512][192] bf16: (Wo_hi|Wo_lo|Wo_hi)^T rows=n
__device__ float g_vg[M_ROWS*128];  // 4MB   v|g fp32 (cols 0-63 v, 64-127 g)
__device__ float g_a[M_ROWS*HH];
__device__ float g_bid[M_ROWS*HH];

// ---------------------------------------------------------------------------
// Helpers
// ---------------------------------------------------------------------------
__device__ __forceinline__ uint32_t smem_u32(const void* p) {
    uint32_t a;
    asm("{ .reg .u64 t; cvta.to.shared.u64 t, %1; cvt.u32.u64 %0, t; }" : "=r"(a) : "l"(p));
    return a;
}
#define SWZ(x) ((x) ^ (((x) >> 3) & 0x70))

__device__ __forceinline__ void cpa16(uint32_t saddr, const void* g) {
    asm volatile("cp.async.cg.shared.global [%0], [%1], 16;" :: "r"(saddr), "l"(g));
}
#define CP_COMMIT() asm volatile("cp.async.commit_group;" ::: "memory")
#define CP_WAIT1()  asm volatile("cp.async.wait_group 1;" ::: "memory")
#define CP_WAIT0()  asm volatile("cp.async.wait_group 0;" ::: "memory")

__device__ __forceinline__ void mma_bf16(float c[4], const uint32_t a[4], const uint32_t b[2]) {
    asm volatile("mma.sync.aligned.m16n8k16.row.col.f32.bf16.bf16.f32 "
        "{%0,%1,%2,%3}, {%4,%5,%6,%7}, {%8,%9}, {%0,%1,%2,%3};"
        : "+f"(c[0]), "+f"(c[1]), "+f"(c[2]), "+f"(c[3])
        : "r"(a[0]), "r"(a[1]), "r"(a[2]), "r"(a[3]), "r"(b[0]), "r"(b[1]));
}

__device__ __forceinline__ void split2(float a, float b, uint32_t& hi, uint32_t& lo) {
    __nv_bfloat16 ha = __float2bfloat16(a), hb = __float2bfloat16(b);
    float ra = a - __bfloat162float(ha), rb = b - __bfloat162float(hb);
    __nv_bfloat162 H, L;
    H.x = ha; H.y = hb;
    L.x = __float2bfloat16(ra); L.y = __float2bfloat16(rb);
    hi = *reinterpret_cast<uint32_t*>(&H);
    lo = *reinterpret_cast<uint32_t*>(&L);
}
__device__ __forceinline__ float neg_inf() { return __int_as_float(0xff800000); }

// ---------------------------------------------------------------------------
// Shared GEMM mainloop: BM=128, BN=128, BK=64, 256 threads (warps 2m x 4n),
// warp tile 64x32, double-buffered cp.async, ldmatrix + mma.sync bf16.
// A row-major [.,lda] (m-major), B row-major [.,ldb] but rows are N (i.e. B^T).
// ---------------------------------------------------------------------------
__device__ __forceinline__ void run_mainloop(
    const __nv_bfloat16* __restrict__ A, const __nv_bfloat16* __restrict__ B,
    int lda, int ldb, int nk, uint32_t sb, float acc[4][4][4])
{
    int tid = threadIdx.x, wid = tid >> 5, lane = tid & 31;
    int wm = (wid & 1) * 64, wn = (wid >> 1) * 32;
    int lr = lane & 7, sel = lane >> 3;
    int arow = wm + lr + (sel & 1) * 8;
    int acol = (sel >> 1) * 16;
    int brow = wn + lr;
    int bcol = (sel & 1) * 16;

    auto load = [&](int kc, int s) {
        uint32_t base = sb + (uint32_t)s * 32768;
        const __nv_bfloat16* Ak = A + kc * 64;
        const __nv_bfloat16* Bk = B + kc * 64;
        #pragma unroll
        for (int j = 0; j < 4; j++) {
            int idx = tid * 4 + j;
            int r = idx >> 3, ch = idx & 7;
            uint32_t so = SWZ((uint32_t)(r * 128 + ch * 16));
            cpa16(base + so,         Ak + (size_t)r * lda + ch * 8);
            cpa16(base + 16384 + so, Bk + (size_t)r * ldb + ch * 8);
        }
        CP_COMMIT();
    };

    load(0, 0);
    if (nk > 1) load(1, 1); else CP_COMMIT();

    for (int kc = 0; kc < nk; kc++) {
        CP_WAIT1();
        __syncthreads();
        uint32_t Ab = sb + (uint32_t)(kc & 1) * 32768;
        uint32_t Bb = Ab + 16384;
        #pragma unroll
        for (int ks = 0; ks < 4; ks++) {
            uint32_t a[4][4], b[4][2];
            #pragma unroll
            for (int mf = 0; mf < 4; mf++) {
                uint32_t addr = Ab + SWZ((uint32_t)((arow + mf * 16) * 128 + acol + ks * 32));
                asm volatile("ldmatrix.sync.aligned.m8n8.x4.shared.b16 {%0,%1,%2,%3}, [%4];"
                    : "=r"(a[mf][0]), "=r"(a[mf][1]), "=r"(a[mf][2]), "=r"(a[mf][3])
                    : "r"(addr));
            }
            #pragma unroll
            for (int nf = 0; nf < 4; nf++) {
                uint32_t addr = Bb + SWZ((uint32_t)((brow + nf * 8) * 128 + bcol + ks * 32));
                asm volatile("ldmatrix.sync.aligned.m8n8.x2.shared.b16 {%0,%1}, [%2];"
                    : "=r"(b[nf][0]), "=r"(b[nf][1])
                    : "r"(addr));
            }
            #pragma unroll
            for (int mf = 0; mf < 4; mf++)
                #pragma unroll
                for (int nf = 0; nf < 4; nf++)
                    mma_bf16(acc[mf][nf], a[mf], b[nf]);
        }
        __syncthreads();
        if (kc + 2 < nk) load(kc + 2, kc & 1); else CP_COMMIT();
    }
    CP_WAIT0();
}

// ---------------------------------------------------------------------------
// K0: convert x -> xcat (hi|hi|lo), fused a = -softplus(x Wa + ba); 1 warp/row
// ---------------------------------------------------------------------------
__global__ void __launch_bounds__(256) convert_x(const float* __restrict__ X,
                                                 const float* __restrict__ Wa,
                                                 const float* __restrict__ ba) {
    int row  = (blockIdx.x * 256 + threadIdx.x) >> 5;
    int lane = threadIdx.x & 31;
    const float* xr = X + (size_t)row * DD;
    int c0 = lane * 16;

    float xv[16];
    #pragma unroll
    for (int i = 0; i < 4; i++) {
        float4 v = *(const float4*)&xr[c0 + i * 4];
        xv[i*4+0] = v.x; xv[i*4+1] = v.y; xv[i*4+2] = v.z; xv[i*4+3] = v.w;
    }

    float4 acc = make_float4(0.f, 0.f, 0.f, 0.f);
    #pragma unroll
    for (int i = 0; i < 16; i++) {
        float4 w = *(const float4*)&Wa[(size_t)(c0 + i) * 4];
        acc.x += xv[i] * w.x; acc.y += xv[i] * w.y;
        acc.z += xv[i] * w.z; acc.w += xv[i] * w.w;
    }

    uint32_t hi[8], lo[8];
    #pragma unroll
    for (int i = 0; i < 8; i++) split2(xv[2*i], xv[2*i+1], hi[i], lo[i]);

    size_t base = (size_t)row * 192 + lane * 2;   // uint4 units; row = 1536 bf16 = 192 uint4
    uint4 h0 = make_uint4(hi[0], hi[1], hi[2], hi[3]);
    uint4 h1 = make_uint4(hi[4], hi[5], hi[6], hi[7]);
    g_xcat[base +   0] = h0;  g_xcat[base +   1] = h1;   // x_hi
    g_xcat[base +  64] = h0;  g_xcat[base +  65] = h1;   // x_hi (dup)
    g_xcat[base + 128] = make_uint4(lo[0], lo[1], lo[2], lo[3]);
    g_xcat[base + 129] = make_uint4(lo[4], lo[5], lo[6], lo[7]);

    #pragma unroll
    for (int off = 16; off > 0; off >>= 1) {
        acc.x += __shfl_down_sync(0xffffffffu, acc.x, off);
        acc.y += __shfl_down_sync(0xffffffffu, acc.y, off);
        acc.z += __shfl_down_sync(0xffffffffu, acc.z, off);
        acc.w += __shfl_down_sync(0xffffffffu, acc.w, off);
    }
    if (lane == 0) {
        float zz[4] = {acc.x + ba[0], acc.y + ba[1], acc.z + ba[2], acc.w + ba[3]};
        #pragma unroll
        for (int h = 0; h < 4; h++) {
            float z = zz[h];
            float sp = fmaxf(z, 0.f) + log1pf(expf(-fabsf(z)));
            g_a[row * HH + h] = -sp;
        }
    }
}

// ---------------------------------------------------------------------------
// K1: pack weights -> wcatT [256][1536] (rows n), woT [512][192] (rows n)
// ---------------------------------------------------------------------------
__global__ void pack_w(const float* __restrict__ Wq, const float* __restrict__ Wk,
                       const float* __restrict__ Wv, const float* __restrict__ Wg,
                       const float* __restrict__ Wo) {
    int idx = blockIdx.x * 256 + threadIdx.x;
    if (idx < 131072) {
        int k = idx >> 8, n = idx & 255;
        float v;
        if      (n < 64)  v = Wq[k*64 + n];
        else if (n < 128) v = Wk[k*64 + (n-64)];
        else if (n < 192) v = Wv[k*64 + (n-128)];
        else              v = Wg[k*64 + (n-192)];
        __nv_bfloat16 h = __float2bfloat16(v);
        __nv_bfloat16 l = __float2bfloat16(v - __bfloat162float(h));
        __nv_bfloat16* W = (__nv_bfloat16*)g_wcatT;
        W[(size_t)n * KQ +        k] = h;   // W_hi
        W[(size_t)n * KQ +  512 + k] = l;   // W_lo
        W[(size_t)n * KQ + 1024 + k] = h;   // W_hi
    } else {
        int j = idx - 131072;              // < 32768
        int k = j >> 9, n = j & 511;
        float v = Wo[(size_t)k * 512 + n];
        __nv_bfloat16 h = __float2bfloat16(v);
        __nv_bfloat16 l = __float2bfloat16(v - __bfloat162float(h));
        __nv_bfloat16* W = (__nv_bfloat16*)g_woT;
        W[(size_t)n * KO +       k] = h;
        W[(size_t)n * KO +  64 + k] = l;
        W[(size_t)n * KO + 128 + k] = h;
    }
}

// ---------------------------------------------------------------------------
// K2: qkvg = xcat @ wcatT^T. grid (2 ntiles, 64 mtiles).
//     ntile 0 -> q|k: stage in smem fp32, compute bid directly.
//     ntile 1 -> v|g: write g_vg.
// ---------------------------------------------------------------------------
__global__ void __launch_bounds__(256) gemm_qkvg_mma() {
    extern __shared__ __align__(1024) char smem[];
    uint32_t sb = smem_u32(smem);
    int tid = threadIdx.x, wid = tid >> 5, lane = tid & 31;
    int ntile = blockIdx.x, mtile = blockIdx.y;

    const __nv_bfloat16* A = ((const __nv_bfloat16*)g_xcat)  + (size_t)mtile * 128 * KQ;
    const __nv_bfloat16* B = ((const __nv_bfloat16*)g_wcatT) + (size_t)ntile * 128 * KQ;

    float acc[4][4][4] = {};
    run_mainloop(A, B, KQ, KQ, 24, sb, acc);

    int wm = (wid & 1) * 64, wn = (wid >> 1) * 32;
    int er = lane >> 2, ec = (lane & 3) * 2;
    int m0 = mtile * 128;

    if (ntile == 0) {
        float* S = (float*)smem;           // 128x128 fp32 = 64KB (xor-swizzled cols)
        int xm = er << 4;
        #pragma unroll
        for (int mf = 0; mf < 4; mf++)
            #pragma unroll
            for (int nf = 0; nf < 4; nf++) {
                int r = wm + mf * 16 + er;
                int c = (wn + nf * 8 + ec) ^ xm;
                *(float2*)&S[r * 128 + c]       = make_float2(acc[mf][nf][0], acc[mf][nf][1]);
                *(float2*)&S[(r + 8) * 128 + c] = make_float2(acc[mf][nf][2], acc[mf][nf][3]);
            }
        __syncthreads();
        #pragma unroll
        for (int it = 0; it < 2; it++) {
            int item = tid * 2 + it;       // 512 items: (m, h)
            int m = item >> 2, h = item & 3;
            int x = (m & 7) << 4;
            const float* q = &S[m * 128 + ((h * 16) ^ x)];
            const float* k = &S[m * 128 + ((64 + h * 16) ^ x)];
            float s = 0.f;
            #pragma unroll
            for (int i = 0; i < 16; i++) s += q[i] * k[i];
            g_bid[(size_t)(m0 + m) * 4 + h] = s * 0.25f;
        }
    } else {
        #pragma unroll
        for (int mf = 0; mf < 4; mf++)
            #pragma unroll
            for (int nf = 0; nf < 4; nf++) {
                int r = m0 + wm + mf * 16 + er;
                int c = wn + nf * 8 + ec;
                *(float2*)&g_vg[(size_t)r * 128 + c]       = make_float2(acc[mf][nf][0], acc[mf][nf][1]);
                *(float2*)&g_vg[(size_t)(r + 8) * 128 + c] = make_float2(acc[mf][nf][2], acc[mf][nf][3]);
            }
    }
}

// ---------------------------------------------------------------------------
// K3: per-(b,h) prefix online-softmax scan + gate; writes zcat (hi|hi|lo)
// ---------------------------------------------------------------------------
__global__ void __launch_bounds__(256) scan_kernel(const float* __restrict__ bg) {
    __shared__ float sp[2048];
    __shared__ float sscan[256];
    __shared__ float sm_[256];
    __shared__ float sd_[256];
    __shared__ float sn_[256 * 16];

    int t = threadIdx.x;
    int bh = blockIdx.x;
    int b = bh >> 2, h = bh & 3;
    int row0 = b * TT + t * 8;

    float la[8];
    {
        float run = 0.f;
        #pragma unroll
        for (int j = 0; j < 8; j++) { run += g_a[(size_t)(row0 + j) * HH + h]; la[j] = run; }
        sscan[t] = run;
    }
    __syncthreads();
    for (int off = 1; off < 256; off <<= 1) {
        float v = (t >= off) ? sscan[t - off] : 0.f;
        __syncthreads();
        sscan[t] += v;
        __syncthreads();
    }
    float exc = (t > 0) ? sscan[t - 1] : 0.f;
    #pragma unroll
    for (int j = 0; j < 8; j++)
        sp[t * 8 + j] = g_bid[(size_t)(row0 + j) * HH + h] - (exc + la[j]);
    __syncthreads();

    float m = neg_inf(), d = 0.f, n[16];
    #pragma unroll
    for (int i = 0; i < 16; i++) n[i] = 0.f;

    #pragma unroll
    for (int j = 0; j < 8; j++) {
        float pi = sp[t * 8 + j];
        const float4* vp = (const float4*)&g_vg[(size_t)(row0 + j) * 128 + h * 16];
        float4 v0 = vp[0], v1 = vp[1], v2 = vp[2], v3 = vp[3];
        float vv[16] = {v0.x,v0.y,v0.z,v0.w, v1.x,v1.y,v1.z,v1.w,
                        v2.x,v2.y,v2.z,v2.w, v3.x,v3.y,v3.z,v3.w};
        if (pi > m) {
            float s = expf(m - pi);
            #pragma unroll
            for (int i = 0; i < 16; i++) n[i] = n[i] * s + vv[i];
            d = d * s + 1.f;
            m = pi;
        } else {
            float w = expf(pi - m);
            #pragma unroll
            for (int i = 0; i < 16; i++) n[i] += w * vv[i];
            d += w;
        }
    }
    sm_[t] = m; sd_[t] = d;
    #pragma unroll
    for (int i = 0; i < 16; i++) sn_[t * 16 + i] = n[i];
    __syncthreads();

    for (int off = 1; off < 256; off <<= 1) {
        float lm = 0.f, ld = 0.f, ln[16];
        #pragma unroll
        for (int i = 0; i < 16; i++) ln[i] = 0.f;
        bool has = (t >= off);
        if (has) {
            lm = sm_[t - off]; ld = sd_[t - off];
            #pragma unroll
            for (int i = 0; i < 16; i++) ln[i] = sn_[(t - off) * 16 + i];
        }
        __syncthreads();
        if (has) {
            float M = fmaxf(lm, m);
            float sl = expf(lm - M), sr = expf(m - M);
            d = ld * sl + d * sr;
            #pragma unroll
            for (int i = 0; i < 16; i++) n[i] = ln[i] * sl + n[i] * sr;
            m = M;
            sm_[t] = m; sd_[t] = d;
            #pragma unroll
            for (int i = 0; i < 16; i++) sn_[t * 16 + i] = n[i];
        }
        __syncthreads();
    }

    float em = neg_inf(), ed = 0.f, en[16];
    #pragma unroll
    for (int i = 0; i < 16; i++) en[i] = 0.f;
    if (t > 0) {
        em = sm_[t - 1]; ed = sd_[t - 1];
        #pragma unroll
        for (int i = 0; i < 16; i++) en[i] = sn_[(t - 1) * 16 + i];
    }

    m = em; d = ed;
    #pragma unroll
    for (int i = 0; i < 16; i++) n[i] = en[i];

    #pragma unroll
    for (int j = 0; j < 8; j++) {
        float pi = sp[t * 8 + j];
        int row = row0 + j;
        const float4* vp = (const float4*)&g_vg[(size_t)row * 128 + h * 16];
        float4 v0 = vp[0], v1 = vp[1], v2 = vp[2], v3 = vp[3];
        float vv[16] = {v0.x,v0.y,v0.z,v0.w, v1.x,v1.y,v1.z,v1.w,
                        v2.x,v2.y,v2.z,v2.w, v3.x,v3.y,v3.z,v3.w};
        if (pi > m) {
            float s = expf(m - pi);
            #pragma unroll
            for (int i = 0; i < 16; i++) n[i] = n[i] * s + vv[i];
            d = d * s + 1.f;
            m = pi;
        } else {
            float w = expf(pi - m);
            #pragma unroll
            for (int i = 0; i < 16; i++) n[i] += w * vv[i];
            d += w;
        }
        float inv = 1.f / d;

        const float4* gp = (const float4*)&g_vg[(size_t)row * 128 + 64 + h * 16];
        float4 g0 = gp[0], g1 = gp[1], g2 = gp[2], g3 = gp[3];
        float gl[16] = {g0.x,g0.y,g0.z,g0.w, g1.x,g1.y,g1.z,g1.w,
                        g2.x,g2.y,g2.z,g2.w, g3.x,g3.y,g3.z,g3.w};
        float out[16];
        #pragma unroll
        for (int i = 0; i < 16; i++) {
            float gate = 1.f / (1.f + expf(-(gl[i] + bg[h * 16 + i])));
            out[i] = n[i] * inv * gate;
        }
        uint32_t hi[8], lo[8];
        #pragma unroll
        for (int i = 0; i < 8; i++) split2(out[2*i], out[2*i+1], hi[i], lo[i]);
        size_t base = (size_t)row * 24 + h * 2;   // uint4 units; row = 192 bf16 = 24 uint4
        uint4 h0 = make_uint4(hi[0], hi[1], hi[2], hi[3]);
        uint4 h1 = make_uint4(hi[4], hi[5], hi[6], hi[7]);
        g_zcat[base +  0] = h0;  g_zcat[base +  1] = h1;   // z_hi
        g_zcat[base +  8] = h0;  g_zcat[base +  9] = h1;   // z_hi (dup)
        g_zcat[base + 16] = make_uint4(lo[0], lo[1], lo[2], lo[3]);
        g_zcat[base + 17] = make_uint4(lo[4], lo[5], lo[6], lo[7]);
    }
}

// ---------------------------------------------------------------------------
// K4: out = zcat @ woT^T. grid (4 ntiles, 64 mtiles), K'=192 (3 chunks).
// ---------------------------------------------------------------------------
__global__ void __launch_bounds__(256) gemm_out_mma(float* __restrict__ O) {
    extern __shared__ __align__(1024) char smem[];
    uint32_t sb = smem_u32(smem);
    int tid = threadIdx.x, wid = tid >> 5, lane = tid & 31;
    int ntile = blockIdx.x, mtile = blockIdx.y;

    const __nv_bfloat16* A = ((const __nv_bfloat16*)g_zcat) + (size_t)mtile * 128 * KO;
    const __nv_bfloat16* B = ((const __nv_bfloat16*)g_woT)  + (size_t)ntile * 128 * KO;

    float acc[4][4][4] = {};
    run_mainloop(A, B, KO, KO, 3, sb, acc);

    int wm = (wid & 1) * 64, wn = (wid >> 1) * 32;
    int er = lane >> 2, ec = (lane & 3) * 2;
    int m0 = mtile * 128, n0 = ntile * 128;

    #pragma unroll
    for (int mf = 0; mf < 4; mf++)
        #pragma unroll
        for (int nf = 0; nf < 4; nf++) {
            int r = m0 + wm + mf * 16 + er;
            int c = n0 + wn + nf * 8 + ec;
            *(float2*)&O[(size_t)r * 512 + c]       = make_float2(acc[mf][nf][0], acc[mf][nf][1]);
            *(float2*)&O[(size_t)(r + 8) * 512 + c] = make_float2(acc[mf][nf][2], acc[mf][nf][3]);
        }
}

// ---------------------------------------------------------------------------
extern "C" void kernel_launch(void* const* d_in, const int* in_sizes, int n_in,
                              void* d_out, int out_size) {
    const float* x  = (const float*)d_in[0];
    const float* Wq = (const float*)d_in[1];
    const float* Wk = (const float*)d_in[2];
    const float* Wv = (const float*)d_in[3];
    const float* Wa = (const float*)d_in[4];
    const float* ba = (const float*)d_in[5];
    const float* Wg = (const float*)d_in[6];
    const float* bg = (const float*)d_in[7];
    const float* Wo = (const float*)d_in[8];
    float* out = (float*)d_out;

    cudaFuncSetAttribute(gemm_qkvg_mma, cudaFuncAttributeMaxDynamicSharedMemorySize, 65536);
    cudaFuncSetAttribute(gemm_out_mma,  cudaFuncAttributeMaxDynamicSharedMemorySize, 65536);

    convert_x<<<1024, 256>>>(x, Wa, ba);
    pack_w<<<640, 256>>>(Wq, Wk, Wv, Wg, Wo);
    gemm_qkvg_mma<<<dim3(2, 64), 256, 65536>>>();
    scan_kernel<<<BATCH * HH, 256>>>(bg);
    gemm_out_mma<<<dim3(4, 64), 256, 65536>>>(out);
}

// round 4
// speedup vs baseline: 1.4533x; 1.3355x over previous
#include <cuda_runtime.h>
#include <cuda_bf16.h>
#include <math.h>
#include <stdint.h>

#define BATCH 4
#define TT 2048
#define DD 512
#define HH 4
#define M_ROWS 8192
#define KQ 1536          // augmented K for qkvg GEMM (hi|hi|lo x hi|lo|hi)
#define KO 192           // augmented K for out GEMM

// ---------------------------------------------------------------------------
// Global scratch (device globals; no allocation allowed)
// ---------------------------------------------------------------------------
__device__ uint4 g_xhi[524288];     // 8MB  [8192][512] bf16
__device__ uint4 g_xlo[524288];     // 8MB
__device__ uint4 g_wcatT[49152];    // 1.5MB [256][1536] bf16 (W_hi|W_lo|W_hi)^T
__device__ uint4 g_zhi[65536];      // 1MB  [8192][64] bf16
__device__ uint4 g_zlo[65536];      // 1MB
__device__ uint4 g_woT[12288];      // 384KB [512][192] bf16 (Wo_hi|Wo_lo|Wo_hi)^T
__device__ float g_vg[M_ROWS*128];  // 4MB  v|g fp32 (cols 0-63 v, 64-127 g)
__device__ float g_a[HH*M_ROWS];    // [h][row]
__device__ float g_bid[HH*M_ROWS];  // [h][row]
__device__ float g_agg[512*20];     // per-chunk aggregates: sumA, m, d, n[16]

// ---------------------------------------------------------------------------
// Helpers
// ---------------------------------------------------------------------------
__device__ __forceinline__ uint32_t smem_u32(const void* p) {
    uint32_t a;
    asm("{ .reg .u64 t; cvta.to.shared.u64 t, %1; cvt.u32.u64 %0, t; }" : "=r"(a) : "l"(p));
    return a;
}
#define SWZ(x) ((x) ^ (((x) >> 3) & 0x70))

__device__ __forceinline__ void cpa16(uint32_t saddr, const void* g) {
    asm volatile("cp.async.cg.shared.global [%0], [%1], 16;" :: "r"(saddr), "l"(g));
}
#define CP_COMMIT() asm volatile("cp.async.commit_group;" ::: "memory")
#define CP_WAIT1()  asm volatile("cp.async.wait_group 1;" ::: "memory")
#define CP_WAIT0()  asm volatile("cp.async.wait_group 0;" ::: "memory")

__device__ __forceinline__ void mma_bf16(float c[4], const uint32_t a[4], const uint32_t b[2]) {
    asm volatile("mma.sync.aligned.m16n8k16.row.col.f32.bf16.bf16.f32 "
        "{%0,%1,%2,%3}, {%4,%5,%6,%7}, {%8,%9}, {%0,%1,%2,%3};"
        : "+f"(c[0]), "+f"(c[1]), "+f"(c[2]), "+f"(c[3])
        : "r"(a[0]), "r"(a[1]), "r"(a[2]), "r"(a[3]), "r"(b[0]), "r"(b[1]));
}

__device__ __forceinline__ void split2(float a, float b, uint32_t& hi, uint32_t& lo) {
    __nv_bfloat16 ha = __float2bfloat16(a), hb = __float2bfloat16(b);
    float ra = a - __bfloat162float(ha), rb = b - __bfloat162float(hb);
    __nv_bfloat162 H, L;
    H.x = ha; H.y = hb;
    L.x = __float2bfloat16(ra); L.y = __float2bfloat16(rb);
    hi = *reinterpret_cast<uint32_t*>(&H);
    lo = *reinterpret_cast<uint32_t*>(&L);
}

#define MSENT -1e30f   // finite sentinel for "-inf" running max (keeps __expf NaN-free)

// online-softmax step (inclusive update), branchless
__device__ __forceinline__ void sm_step(float& m, float& d, float n[16],
                                        float p, const float* v) {
    float4 v0 = *(const float4*)&v[0],  v1 = *(const float4*)&v[4];
    float4 v2 = *(const float4*)&v[8],  v3 = *(const float4*)&v[12];
    float vv[16] = {v0.x,v0.y,v0.z,v0.w, v1.x,v1.y,v1.z,v1.w,
                    v2.x,v2.y,v2.z,v2.w, v3.x,v3.y,v3.z,v3.w};
    float M = fmaxf(m, p);
    float sm = __expf(m - M), sp = __expf(p - M);
    d = d * sm + sp;
    #pragma unroll
    for (int i = 0; i < 16; i++) n[i] = n[i] * sm + vv[i] * sp;
    m = M;
}

// state combine: self(right) <- other(left) ⊕ self  (commutative)
__device__ __forceinline__ void sm_comb(float& m, float& d, float n[16],
                                        float om, float od, const float on[16]) {
    float M = fmaxf(om, m);
    float so = __expf(om - M), ss = __expf(m - M);
    d = od * so + d * ss;
    #pragma unroll
    for (int i = 0; i < 16; i++) n[i] = on[i] * so + n[i] * ss;
    m = M;
}

// ---------------------------------------------------------------------------
// Shared GEMM mainloop: BM=128, BN=128, BK=64, 256 threads (warps 2m x 4n),
// warp tile 64x32, double-buffered cp.async, ldmatrix + mma.sync bf16.
// getA(kc) -> pointer to the 128 x 64 A tile for K-chunk kc (row stride lda).
// B row-major with rows = N (B^T), chunk at B + kc*64.
// ---------------------------------------------------------------------------
template <class FA>
__device__ __forceinline__ void run_mainloop(
    FA getA, const __nv_bfloat16* __restrict__ B,
    int lda, int ldb, int nk, uint32_t sb, float acc[4][4][4])
{
    int tid = threadIdx.x, wid = tid >> 5, lane = tid & 31;
    int wm = (wid & 1) * 64, wn = (wid >> 1) * 32;
    int lr = lane & 7, sel = lane >> 3;
    int arow = wm + lr + (sel & 1) * 8;
    int acol = (sel >> 1) * 16;
    int brow = wn + lr;
    int bcol = (sel & 1) * 16;

    auto load = [&](int kc, int s) {
        uint32_t base = sb + (uint32_t)s * 32768;
        const __nv_bfloat16* Ak = getA(kc);
        const __nv_bfloat16* Bk = B + kc * 64;
        #pragma unroll
        for (int j = 0; j < 4; j++) {
            int idx = tid * 4 + j;
            int r = idx >> 3, ch = idx & 7;
            uint32_t so = SWZ((uint32_t)(r * 128 + ch * 16));
            cpa16(base + so,         Ak + (size_t)r * lda + ch * 8);
            cpa16(base + 16384 + so, Bk + (size_t)r * ldb + ch * 8);
        }
        CP_COMMIT();
    };

    load(0, 0);
    if (nk > 1) load(1, 1); else CP_COMMIT();

    for (int kc = 0; kc < nk; kc++) {
        CP_WAIT1();
        __syncthreads();
        uint32_t Ab = sb + (uint32_t)(kc & 1) * 32768;
        uint32_t Bb = Ab + 16384;
        #pragma unroll
        for (int ks = 0; ks < 4; ks++) {
            uint32_t a[4][4], b[4][2];
            #pragma unroll
            for (int mf = 0; mf < 4; mf++) {
                uint32_t addr = Ab + SWZ((uint32_t)((arow + mf * 16) * 128 + acol + ks * 32));
                asm volatile("ldmatrix.sync.aligned.m8n8.x4.shared.b16 {%0,%1,%2,%3}, [%4];"
                    : "=r"(a[mf][0]), "=r"(a[mf][1]), "=r"(a[mf][2]), "=r"(a[mf][3])
                    : "r"(addr));
            }
            #pragma unroll
            for (int nf = 0; nf < 4; nf++) {
                uint32_t addr = Bb + SWZ((uint32_t)((brow + nf * 8) * 128 + bcol + ks * 32));
                asm volatile("ldmatrix.sync.aligned.m8n8.x2.shared.b16 {%0,%1}, [%2];"
                    : "=r"(b[nf][0]), "=r"(b[nf][1])
                    : "r"(addr));
            }
            #pragma unroll
            for (int mf = 0; mf < 4; mf++)
                #pragma unroll
                for (int nf = 0; nf < 4; nf++)
                    mma_bf16(acc[mf][nf], a[mf], b[nf]);
        }
        __syncthreads();
        if (kc + 2 < nk) load(kc + 2, kc & 1); else CP_COMMIT();
    }
    CP_WAIT0();
}

// ---------------------------------------------------------------------------
// K0: convert x -> (x_hi, x_lo), fused a = -softplus(x Wa + ba); 1 warp/row
// ---------------------------------------------------------------------------
__global__ void __launch_bounds__(256) convert_x(const float* __restrict__ X,
                                                 const float* __restrict__ Wa,
                                                 const float* __restrict__ ba) {
    int row  = (blockIdx.x * 256 + threadIdx.x) >> 5;
    int lane = threadIdx.x & 31;
    const float* xr = X + (size_t)row * DD;
    int c0 = lane * 16;

    float xv[16];
    #pragma unroll
    for (int i = 0; i < 4; i++) {
        float4 v = *(const float4*)&xr[c0 + i * 4];
        xv[i*4+0] = v.x; xv[i*4+1] = v.y; xv[i*4+2] = v.z; xv[i*4+3] = v.w;
    }

    float4 acc = make_float4(0.f, 0.f, 0.f, 0.f);
    #pragma unroll
    for (int i = 0; i < 16; i++) {
        float4 w = *(const float4*)&Wa[(size_t)(c0 + i) * 4];
        acc.x += xv[i] * w.x; acc.y += xv[i] * w.y;
        acc.z += xv[i] * w.z; acc.w += xv[i] * w.w;
    }

    uint32_t hi[8], lo[8];
    #pragma unroll
    for (int i = 0; i < 8; i++) split2(xv[2*i], xv[2*i+1], hi[i], lo[i]);

    size_t base = (size_t)row * 64 + lane * 2;
    g_xhi[base + 0] = make_uint4(hi[0], hi[1], hi[2], hi[3]);
    g_xhi[base + 1] = make_uint4(hi[4], hi[5], hi[6], hi[7]);
    g_xlo[base + 0] = make_uint4(lo[0], lo[1], lo[2], lo[3]);
    g_xlo[base + 1] = make_uint4(lo[4], lo[5], lo[6], lo[7]);

    #pragma unroll
    for (int off = 16; off > 0; off >>= 1) {
        acc.x += __shfl_down_sync(0xffffffffu, acc.x, off);
        acc.y += __shfl_down_sync(0xffffffffu, acc.y, off);
        acc.z += __shfl_down_sync(0xffffffffu, acc.z, off);
        acc.w += __shfl_down_sync(0xffffffffu, acc.w, off);
    }
    if (lane == 0) {
        float zz[4] = {acc.x + ba[0], acc.y + ba[1], acc.z + ba[2], acc.w + ba[3]};
        #pragma unroll
        for (int h = 0; h < 4; h++) {
            float z = zz[h];
            float sp = fmaxf(z, 0.f) + log1pf(expf(-fabsf(z)));
            g_a[h * M_ROWS + row] = -sp;
        }
    }
}

// ---------------------------------------------------------------------------
// K1: pack weights -> wcatT [256][1536] (rows n), woT [512][192] (rows n)
// ---------------------------------------------------------------------------
__global__ void pack_w(const float* __restrict__ Wq, const float* __restrict__ Wk,
                       const float* __restrict__ Wv, const float* __restrict__ Wg,
                       const float* __restrict__ Wo) {
    int idx = blockIdx.x * 256 + threadIdx.x;
    if (idx < 131072) {
        int k = idx >> 8, n = idx & 255;
        float v;
        if      (n < 64)  v = Wq[k*64 + n];
        else if (n < 128) v = Wk[k*64 + (n-64)];
        else if (n < 192) v = Wv[k*64 + (n-128)];
        else              v = Wg[k*64 + (n-192)];
        __nv_bfloat16 h = __float2bfloat16(v);
        __nv_bfloat16 l = __float2bfloat16(v - __bfloat162float(h));
        __nv_bfloat16* W = (__nv_bfloat16*)g_wcatT;
        W[(size_t)n * KQ +        k] = h;   // W_hi
        W[(size_t)n * KQ +  512 + k] = l;   // W_lo
        W[(size_t)n * KQ + 1024 + k] = h;   // W_hi
    } else {
        int j = idx - 131072;              // < 32768
        int k = j >> 9, n = j & 511;
        float v = Wo[(size_t)k * 512 + n];
        __nv_bfloat16 h = __float2bfloat16(v);
        __nv_bfloat16 l = __float2bfloat16(v - __bfloat162float(h));
        __nv_bfloat16* W = (__nv_bfloat16*)g_woT;
        W[(size_t)n * KO +       k] = h;
        W[(size_t)n * KO +  64 + k] = l;
        W[(size_t)n * KO + 128 + k] = h;
    }
}

// ---------------------------------------------------------------------------
// K2: qkvg GEMM. grid (2 ntiles, 64 mtiles). ntile0 -> bid, ntile1 -> v|g.
// ---------------------------------------------------------------------------
__global__ void __launch_bounds__(256) gemm_qkvg_mma() {
    extern __shared__ __align__(1024) char smem[];
    uint32_t sb = smem_u32(smem);
    int tid = threadIdx.x, wid = tid >> 5, lane = tid & 31;
    int ntile = blockIdx.x, mtile = blockIdx.y;

    const __nv_bfloat16* B = ((const __nv_bfloat16*)g_wcatT) + (size_t)ntile * 128 * KQ;
    size_t aoff = (size_t)mtile * 128 * 512;
    auto getA = [&](int kc) -> const __nv_bfloat16* {
        const __nv_bfloat16* base = (kc < 16) ? (const __nv_bfloat16*)g_xhi
                                              : (const __nv_bfloat16*)g_xlo;
        int kk = (kc < 8) ? kc : ((kc < 16) ? kc - 8 : kc - 16);
        return base + aoff + kk * 64;
    };

    float acc[4][4][4] = {};
    run_mainloop(getA, B, 512, KQ, 24, sb, acc);

    int wm = (wid & 1) * 64, wn = (wid >> 1) * 32;
    int er = lane >> 2, ec = (lane & 3) * 2;
    int m0 = mtile * 128;

    if (ntile == 0) {
        float* S = (float*)smem;           // 128x128 fp32, xor-swizzled cols
        int xm = er << 4;
        #pragma unroll
        for (int mf = 0; mf < 4; mf++)
            #pragma unroll
            for (int nf = 0; nf < 4; nf++) {
                int r = wm + mf * 16 + er;
                int c = (wn + nf * 8 + ec) ^ xm;
                *(float2*)&S[r * 128 + c]       = make_float2(acc[mf][nf][0], acc[mf][nf][1]);
                *(float2*)&S[(r + 8) * 128 + c] = make_float2(acc[mf][nf][2], acc[mf][nf][3]);
            }
        __syncthreads();
        #pragma unroll
        for (int it = 0; it < 2; it++) {
            int item = tid * 2 + it;       // (m, h)
            int m = item >> 2, h = item & 3;
            int x = (m & 7) << 4;
            const float* q = &S[m * 128 + ((h * 16) ^ x)];
            const float* k = &S[m * 128 + ((64 + h * 16) ^ x)];
            float s = 0.f;
            #pragma unroll
            for (int i = 0; i < 16; i++) s += q[i] * k[i];
            g_bid[(size_t)h * M_ROWS + m0 + m] = s * 0.25f;
        }
    } else {
        #pragma unroll
        for (int mf = 0; mf < 4; mf++)
            #pragma unroll
            for (int nf = 0; nf < 4; nf++) {
                int r = m0 + wm + mf * 16 + er;
                int c = wn + nf * 8 + ec;
                *(float2*)&g_vg[(size_t)r * 128 + c]       = make_float2(acc[mf][nf][0], acc[mf][nf][1]);
                *(float2*)&g_vg[(size_t)(r + 8) * 128 + c] = make_float2(acc[mf][nf][2], acc[mf][nf][3]);
            }
    }
}

// ---------------------------------------------------------------------------
// Scan: 512 chunks (16 bh x 32 chunks of 64 steps), 1 warp per chunk,
//       2 steps per lane, register/shfl-only.
// ---------------------------------------------------------------------------
#define WSHFL_STATE(om, od, on, off)                                        \
    do {                                                                    \
        om = __shfl_up_sync(0xffffffffu, m, off);                           \
        od = __shfl_up_sync(0xffffffffu, d, off);                           \
        _Pragma("unroll")                                                   \
        for (int _i = 0; _i < 16; _i++)                                     \
            on[_i] = __shfl_up_sync(0xffffffffu, n[_i], off);               \
    } while (0)

// S1: per-chunk aggregates
__global__ void __launch_bounds__(128) scan_part1() {
    int warp = threadIdx.x >> 5, lane = threadIdx.x & 31;
    int chunk = blockIdx.x * 4 + warp;          // 0..511
    int bh = chunk >> 5, c = chunk & 31;
    int b = bh >> 2, h = bh & 3;
    int row = b * TT + c * 64 + lane * 2;

    const float* A   = g_a   + (size_t)h * M_ROWS;
    const float* BID = g_bid + (size_t)h * M_ROWS;
    float a0 = A[row], a1 = A[row + 1];
    float la = a0 + a1;
    float incl = la;
    #pragma unroll
    for (int off = 1; off < 32; off <<= 1) {
        float o = __shfl_up_sync(0xffffffffu, incl, off);
        if (lane >= off) incl += o;
    }
    float exc = incl - la;
    float p0 = BID[row]     - (exc + a0);
    float p1 = BID[row + 1] - (exc + a0 + a1);

    float m = MSENT, d = 0.f, n[16];
    #pragma unroll
    for (int i = 0; i < 16; i++) n[i] = 0.f;
    sm_step(m, d, n, p0, &g_vg[(size_t)row * 128 + h * 16]);
    sm_step(m, d, n, p1, &g_vg[(size_t)(row + 1) * 128 + h * 16]);

    #pragma unroll
    for (int off = 1; off < 32; off <<= 1) {
        float om, od, on[16];
        WSHFL_STATE(om, od, on, off);
        if (lane >= off) sm_comb(m, d, n, om, od, on);
    }
    if (lane == 31) {
        float* ag = g_agg + (size_t)chunk * 20;
        ag[0] = incl; ag[1] = m; ag[2] = d;
        #pragma unroll
        for (int i = 0; i < 16; i++) ag[3 + i] = n[i];
    }
}

// S2: prefix from aggregates + replay + gate + z split
__global__ void __launch_bounds__(128) scan_part2(const float* __restrict__ bg) {
    int warp = threadIdx.x >> 5, lane = threadIdx.x & 31;
    int chunk = blockIdx.x * 4 + warp;
    int bh = chunk >> 5, c = chunk & 31;
    int b = bh >> 2, h = bh & 3;
    int row = b * TT + c * 64 + lane * 2;

    // --- cross-chunk exclusive prefix (lane l holds chunk l of this bh) ---
    float Pm, Pd, Pn[16], prefAc;
    {
        const float* ag = g_agg + (size_t)(bh * 32 + lane) * 20;
        float sA = ag[0];
        float m = ag[1], d = ag[2], n[16];
        #pragma unroll
        for (int i = 0; i < 16; i++) n[i] = ag[3 + i];

        float cum = sA;
        #pragma unroll
        for (int off = 1; off < 32; off <<= 1) {
            float o = __shfl_up_sync(0xffffffffu, cum, off);
            if (lane >= off) cum += o;
        }
        m -= (cum - sA);                 // chunk state into global frame
        #pragma unroll
        for (int off = 1; off < 32; off <<= 1) {
            float om, od, on[16];
            WSHFL_STATE(om, od, on, off);
            if (lane >= off) sm_comb(m, d, n, om, od, on);
        }
        int src = (c == 0) ? 0 : (c - 1);
        Pm = __shfl_sync(0xffffffffu, m, src);
        Pd = __shfl_sync(0xffffffffu, d, src);
        #pragma unroll
        for (int i = 0; i < 16; i++) Pn[i] = __shfl_sync(0xffffffffu, n[i], src);
        prefAc = __shfl_sync(0xffffffffu, cum, src);
        if (c == 0) {
            Pm = MSENT; Pd = 0.f; prefAc = 0.f;
            #pragma unroll
            for (int i = 0; i < 16; i++) Pn[i] = 0.f;
        }
        Pm += prefAc;                    // into this chunk's local frame
    }

    // --- rebuild lane locals (local frame) ---
    const float* A   = g_a   + (size_t)h * M_ROWS;
    const float* BID = g_bid + (size_t)h * M_ROWS;
    float a0 = A[row], a1 = A[row + 1];
    float la = a0 + a1;
    float incl = la;
    #pragma unroll
    for (int off = 1; off < 32; off <<= 1) {
        float o = __shfl_up_sync(0xffffffffu, incl, off);
        if (lane >= off) incl += o;
    }
    float exc = incl - la;
    float p0 = BID[row]     - (exc + a0);
    float p1 = BID[row + 1] - (exc + a0 + a1);

    float m = MSENT, d = 0.f, n[16];
    #pragma unroll
    for (int i = 0; i < 16; i++) n[i] = 0.f;
    sm_step(m, d, n, p0, &g_vg[(size_t)row * 128 + h * 16]);
    sm_step(m, d, n, p1, &g_vg[(size_t)(row + 1) * 128 + h * 16]);
    #pragma unroll
    for (int off = 1; off < 32; off <<= 1) {
        float om, od, on[16];
        WSHFL_STATE(om, od, on, off);
        if (lane >= off) sm_comb(m, d, n, om, od, on);
    }
    // exclusive lane prefix within chunk
    float em = __shfl_up_sync(0xffffffffu, m, 1);
    float ed = __shfl_up_sync(0xffffffffu, d, 1);
    float en[16];
    #pragma unroll
    for (int i = 0; i < 16; i++) en[i] = __shfl_up_sync(0xffffffffu, n[i], 1);
    if (lane == 0) {
        em = MSENT; ed = 0.f;
        #pragma unroll
        for (int i = 0; i < 16; i++) en[i] = 0.f;
    }
    sm_comb(em, ed, en, Pm, Pd, Pn);     // full exclusive state

    float bgv[16];
    #pragma unroll
    for (int i = 0; i < 16; i++) bgv[i] = bg[h * 16 + i];

    float ps[2] = {p0, p1};
    #pragma unroll
    for (int j = 0; j < 2; j++) {
        int r = row + j;
        sm_step(em, ed, en, ps[j], &g_vg[(size_t)r * 128 + h * 16]);
        float inv = __fdividef(1.f, ed);

        const float* gp = &g_vg[(size_t)r * 128 + 64 + h * 16];
        float4 g0 = *(const float4*)&gp[0],  g1 = *(const float4*)&gp[4];
        float4 g2 = *(const float4*)&gp[8],  g3 = *(const float4*)&gp[12];
        float gl[16] = {g0.x,g0.y,g0.z,g0.w, g1.x,g1.y,g1.z,g1.w,
                        g2.x,g2.y,g2.z,g2.w, g3.x,g3.y,g3.z,g3.w};
        float out[16];
        #pragma unroll
        for (int i = 0; i < 16; i++) {
            float gate = __fdividef(1.f, 1.f + __expf(-(gl[i] + bgv[i])));
            out[i] = en[i] * inv * gate;
        }
        uint32_t hi[8], lo[8];
        #pragma unroll
        for (int i = 0; i < 8; i++) split2(out[2*i], out[2*i+1], hi[i], lo[i]);
        size_t zb = (size_t)r * 8 + h * 2;
        g_zhi[zb + 0] = make_uint4(hi[0], hi[1], hi[2], hi[3]);
        g_zhi[zb + 1] = make_uint4(hi[4], hi[5], hi[6], hi[7]);
        g_zlo[zb + 0] = make_uint4(lo[0], lo[1], lo[2], lo[3]);
        g_zlo[zb + 1] = make_uint4(lo[4], lo[5], lo[6], lo[7]);
    }
}

// ---------------------------------------------------------------------------
// K4: out = z @ Wo. grid (4 ntiles, 64 mtiles), K'=192 (3 chunks: hi, hi, lo).
// ---------------------------------------------------------------------------
__global__ void __launch_bounds__(256) gemm_out_mma(float* __restrict__ O) {
    extern __shared__ __align__(1024) char smem[];
    uint32_t sb = smem_u32(smem);
    int tid = threadIdx.x, wid = tid >> 5, lane = tid & 31;
    int ntile = blockIdx.x, mtile = blockIdx.y;

    const __nv_bfloat16* B = ((const __nv_bfloat16*)g_woT) + (size_t)ntile * 128 * KO;
    size_t aoff = (size_t)mtile * 128 * 64;
    auto getA = [&](int kc) -> const __nv_bfloat16* {
        return ((kc < 2) ? (const __nv_bfloat16*)g_zhi
                         : (const __nv_bfloat16*)g_zlo) + aoff;
    };

    float acc[4][4][4] = {};
    run_mainloop(getA, B, 64, KO, 3, sb, acc);

    int wm = (wid & 1) * 64, wn = (wid >> 1) * 32;
    int er = lane >> 2, ec = (lane & 3) * 2;
    int m0 = mtile * 128, n0 = ntile * 128;

    #pragma unroll
    for (int mf = 0; mf < 4; mf++)
        #pragma unroll
        for (int nf = 0; nf < 4; nf++) {
            int r = m0 + wm + mf * 16 + er;
            int c = n0 + wn + nf * 8 + ec;
            *(float2*)&O[(size_t)r * 512 + c]       = make_float2(acc[mf][nf][0], acc[mf][nf][1]);
            *(float2*)&O[(size_t)(r + 8) * 512 + c] = make_float2(acc[mf][nf][2], acc[mf][nf][3]);
        }
}

// ---------------------------------------------------------------------------
extern "C" void kernel_launch(void* const* d_in, const int* in_sizes, int n_in,
                              void* d_out, int out_size) {
    const float* x  = (const float*)d_in[0];
    const float* Wq = (const float*)d_in[1];
    const float* Wk = (const float*)d_in[2];
    const float* Wv = (const float*)d_in[3];
    const float* Wa = (const float*)d_in[4];
    const float* ba = (const float*)d_in[5];
    const float* Wg = (const float*)d_in[6];
    const float* bg = (const float*)d_in[7];
    const float* Wo = (const float*)d_in[8];
    float* out = (float*)d_out;

    cudaFuncSetAttribute(gemm_qkvg_mma, cudaFuncAttributeMaxDynamicSharedMemorySize, 65536);
    cudaFuncSetAttribute(gemm_out_mma,  cudaFuncAttributeMaxDynamicSharedMemorySize, 65536);

    convert_x<<<1024, 256>>>(x, Wa, ba);
    pack_w<<<640, 256>>>(Wq, Wk, Wv, Wg, Wo);
    gemm_qkvg_mma<<<dim3(2, 64), 256, 65536>>>();
    scan_part1<<<128, 128>>>();
    scan_part2<<<128, 128>>>(bg);
    gemm_out_mma<<<dim3(4, 64), 256, 65536>>>(out);
}

// round 5
// speedup vs baseline: 1.5314x; 1.0537x over previous
#include <cuda_runtime.h>
#include <cuda_bf16.h>
#include <math.h>
#include <stdint.h>

#define BATCH 4
#define TT 2048
#define DD 512
#define HH 4
#define M_ROWS 8192
#define KQ 1536          // augmented K for qkvg GEMM (hi|hi|lo x hi|lo|hi)
#define KO 192           // augmented K for out GEMM

// ---------------------------------------------------------------------------
// Global scratch (device globals; no allocation allowed)
// ---------------------------------------------------------------------------
__device__ uint4 g_xhi[524288];     // 8MB  [8192][512] bf16
__device__ uint4 g_xlo[524288];     // 8MB
__device__ uint4 g_wcatT[49152];    // 1.5MB [256][1536] bf16 (W_hi|W_lo|W_hi)^T
__device__ uint4 g_zhi[65536];      // 1MB  [8192][64] bf16
__device__ uint4 g_zlo[65536];      // 1MB
__device__ uint4 g_woT[12288];      // 384KB [512][192] bf16 (Wo_hi|Wo_lo|Wo_hi)^T
__device__ float g_vg[M_ROWS*128];  // 4MB  v|g fp32 (cols 0-63 v, 64-127 g)
__device__ float g_a[HH*M_ROWS];    // [h][row]
__device__ float g_bid[HH*M_ROWS];  // [h][row]
// scan intermediates (SoA by global lane id gl = chunk*32 + lane)
__device__ float g_p0[16384], g_p1[16384];
__device__ float g_sm[16384], g_sd[16384];
__device__ float g_sn[16][16384];
__device__ float g_aggA[512];       // per-chunk total sum of a

// ---------------------------------------------------------------------------
// Helpers
// ---------------------------------------------------------------------------
__device__ __forceinline__ uint32_t smem_u32(const void* p) {
    uint32_t a;
    asm("{ .reg .u64 t; cvta.to.shared.u64 t, %1; cvt.u32.u64 %0, t; }" : "=r"(a) : "l"(p));
    return a;
}
#define SWZ(x) ((x) ^ (((x) >> 3) & 0x70))

__device__ __forceinline__ void cpa16(uint32_t saddr, const void* g) {
    asm volatile("cp.async.cg.shared.global [%0], [%1], 16;" :: "r"(saddr), "l"(g));
}
#define CP_COMMIT() asm volatile("cp.async.commit_group;" ::: "memory")
#define CP_WAIT1()  asm volatile("cp.async.wait_group 1;" ::: "memory")
#define CP_WAIT0()  asm volatile("cp.async.wait_group 0;" ::: "memory")

__device__ __forceinline__ void mma_bf16(float c[4], const uint32_t a[4], const uint32_t b[2]) {
    asm volatile("mma.sync.aligned.m16n8k16.row.col.f32.bf16.bf16.f32 "
        "{%0,%1,%2,%3}, {%4,%5,%6,%7}, {%8,%9}, {%0,%1,%2,%3};"
        : "+f"(c[0]), "+f"(c[1]), "+f"(c[2]), "+f"(c[3])
        : "r"(a[0]), "r"(a[1]), "r"(a[2]), "r"(a[3]), "r"(b[0]), "r"(b[1]));
}

__device__ __forceinline__ void split2(float a, float b, uint32_t& hi, uint32_t& lo) {
    __nv_bfloat16 ha = __float2bfloat16(a), hb = __float2bfloat16(b);
    float ra = a - __bfloat162float(ha), rb = b - __bfloat162float(hb);
    __nv_bfloat162 H, L;
    H.x = ha; H.y = hb;
    L.x = __float2bfloat16(ra); L.y = __float2bfloat16(rb);
    hi = *reinterpret_cast<uint32_t*>(&H);
    lo = *reinterpret_cast<uint32_t*>(&L);
}

#define MSENT -1e30f

// online-softmax step (inclusive update), branchless
__device__ __forceinline__ void sm_step(float& m, float& d, float n[16],
                                        float p, const float* v) {
    float4 v0 = *(const float4*)&v[0],  v1 = *(const float4*)&v[4];
    float4 v2 = *(const float4*)&v[8],  v3 = *(const float4*)&v[12];
    float vv[16] = {v0.x,v0.y,v0.z,v0.w, v1.x,v1.y,v1.z,v1.w,
                    v2.x,v2.y,v2.z,v2.w, v3.x,v3.y,v3.z,v3.w};
    float M = fmaxf(m, p);
    float sm = __expf(m - M), sp = __expf(p - M);
    d = d * sm + sp;
    #pragma unroll
    for (int i = 0; i < 16; i++) n[i] = n[i] * sm + vv[i] * sp;
    m = M;
}

// state combine: self(right) <- other(left) ⊕ self
__device__ __forceinline__ void sm_comb(float& m, float& d, float n[16],
                                        float om, float od, const float on[16]) {
    float M = fmaxf(om, m);
    float so = __expf(om - M), ss = __expf(m - M);
    d = od * so + d * ss;
    #pragma unroll
    for (int i = 0; i < 16; i++) n[i] = on[i] * so + n[i] * ss;
    m = M;
}

// ---------------------------------------------------------------------------
// Shared GEMM mainloop: BM=128, BN=128, BK=64, 256 threads (warps 2m x 4n),
// warp tile 64x32, THREE-stage cp.async pipeline, 1 syncthreads per chunk.
// getA(kc) -> pointer to 128 x 64 A tile for K-chunk kc (row stride lda).
// B row-major with rows = N (B^T), chunk at B + kc*64.
// Stage s at sb + s*32768 (A 16KB | B 16KB).
// ---------------------------------------------------------------------------
template <class FA>
__device__ __forceinline__ void run_mainloop(
    FA getA, const __nv_bfloat16* __restrict__ B,
    int lda, int ldb, int nk, uint32_t sb, float acc[4][4][4])
{
    int tid = threadIdx.x, wid = tid >> 5, lane = tid & 31;
    int wm = (wid & 1) * 64, wn = (wid >> 1) * 32;
    int lr = lane & 7, sel = lane >> 3;
    int arow = wm + lr + (sel & 1) * 8;
    int acol = (sel >> 1) * 16;
    int brow = wn + lr;
    int bcol = (sel & 1) * 16;

    auto load = [&](int kc, int s) {
        uint32_t base = sb + (uint32_t)s * 32768;
        const __nv_bfloat16* Ak = getA(kc);
        const __nv_bfloat16* Bk = B + kc * 64;
        #pragma unroll
        for (int j = 0; j < 4; j++) {
            int idx = tid * 4 + j;
            int r = idx >> 3, ch = idx & 7;
            uint32_t so = SWZ((uint32_t)(r * 128 + ch * 16));
            cpa16(base + so,         Ak + (size_t)r * lda + ch * 8);
            cpa16(base + 16384 + so, Bk + (size_t)r * ldb + ch * 8);
        }
        CP_COMMIT();
    };

    load(0, 0);
    if (nk > 1) load(1, 1); else CP_COMMIT();

    for (int kc = 0; kc < nk; kc++) {
        CP_WAIT1();               // all but most-recent group retired -> chunk kc ready
        __syncthreads();          // stage (kc+2)%3 free (compute kc-1 done everywhere)
        if (kc + 2 < nk) load(kc + 2, (kc + 2) % 3); else CP_COMMIT();

        uint32_t Ab = sb + (uint32_t)(kc % 3) * 32768;
        uint32_t Bb = Ab + 16384;
        #pragma unroll
        for (int ks = 0; ks < 4; ks++) {
            uint32_t a[4][4], b[4][2];
            #pragma unroll
            for (int mf = 0; mf < 4; mf++) {
                uint32_t addr = Ab + SWZ((uint32_t)((arow + mf * 16) * 128 + acol + ks * 32));
                asm volatile("ldmatrix.sync.aligned.m8n8.x4.shared.b16 {%0,%1,%2,%3}, [%4];"
                    : "=r"(a[mf][0]), "=r"(a[mf][1]), "=r"(a[mf][2]), "=r"(a[mf][3])
                    : "r"(addr));
            }
            #pragma unroll
            for (int nf = 0; nf < 4; nf++) {
                uint32_t addr = Bb + SWZ((uint32_t)((brow + nf * 8) * 128 + bcol + ks * 32));
                asm volatile("ldmatrix.sync.aligned.m8n8.x2.shared.b16 {%0,%1}, [%2];"
                    : "=r"(b[nf][0]), "=r"(b[nf][1])
                    : "r"(addr));
            }
            #pragma unroll
            for (int mf = 0; mf < 4; mf++)
                #pragma unroll
                for (int nf = 0; nf < 4; nf++)
                    mma_bf16(acc[mf][nf], a[mf], b[nf]);
        }
    }
    CP_WAIT0();
}

// ---------------------------------------------------------------------------
// K0: merged setup. Blocks [0,1024): convert x -> (x_hi,x_lo) + a-projection.
//     Blocks [1024,1664): pack weights.
// ---------------------------------------------------------------------------
__global__ void __launch_bounds__(256) setup_kernel(
    const float* __restrict__ X,  const float* __restrict__ Wa,
    const float* __restrict__ ba, const float* __restrict__ Wq,
    const float* __restrict__ Wk, const float* __restrict__ Wv,
    const float* __restrict__ Wg, const float* __restrict__ Wo)
{
    if (blockIdx.x < 1024) {
        int row  = (blockIdx.x * 256 + threadIdx.x) >> 5;
        int lane = threadIdx.x & 31;
        const float* xr = X + (size_t)row * DD;
        int c0 = lane * 16;

        float xv[16];
        #pragma unroll
        for (int i = 0; i < 4; i++) {
            float4 v = *(const float4*)&xr[c0 + i * 4];
            xv[i*4+0] = v.x; xv[i*4+1] = v.y; xv[i*4+2] = v.z; xv[i*4+3] = v.w;
        }

        float4 acc = make_float4(0.f, 0.f, 0.f, 0.f);
        #pragma unroll
        for (int i = 0; i < 16; i++) {
            float4 w = *(const float4*)&Wa[(size_t)(c0 + i) * 4];
            acc.x += xv[i] * w.x; acc.y += xv[i] * w.y;
            acc.z += xv[i] * w.z; acc.w += xv[i] * w.w;
        }

        uint32_t hi[8], lo[8];
        #pragma unroll
        for (int i = 0; i < 8; i++) split2(xv[2*i], xv[2*i+1], hi[i], lo[i]);

        size_t base = (size_t)row * 64 + lane * 2;
        g_xhi[base + 0] = make_uint4(hi[0], hi[1], hi[2], hi[3]);
        g_xhi[base + 1] = make_uint4(hi[4], hi[5], hi[6], hi[7]);
        g_xlo[base + 0] = make_uint4(lo[0], lo[1], lo[2], lo[3]);
        g_xlo[base + 1] = make_uint4(lo[4], lo[5], lo[6], lo[7]);

        #pragma unroll
        for (int off = 16; off > 0; off >>= 1) {
            acc.x += __shfl_down_sync(0xffffffffu, acc.x, off);
            acc.y += __shfl_down_sync(0xffffffffu, acc.y, off);
            acc.z += __shfl_down_sync(0xffffffffu, acc.z, off);
            acc.w += __shfl_down_sync(0xffffffffu, acc.w, off);
        }
        if (lane == 0) {
            float zz[4] = {acc.x + ba[0], acc.y + ba[1], acc.z + ba[2], acc.w + ba[3]};
            #pragma unroll
            for (int h = 0; h < 4; h++) {
                float z = zz[h];
                float sp = fmaxf(z, 0.f) + log1pf(expf(-fabsf(z)));
                g_a[h * M_ROWS + row] = -sp;
            }
        }
    } else {
        int idx = (blockIdx.x - 1024) * 256 + threadIdx.x;
        if (idx < 131072) {
            int k = idx >> 8, n = idx & 255;
            float v;
            if      (n < 64)  v = Wq[k*64 + n];
            else if (n < 128) v = Wk[k*64 + (n-64)];
            else if (n < 192) v = Wv[k*64 + (n-128)];
            else              v = Wg[k*64 + (n-192)];
            __nv_bfloat16 h = __float2bfloat16(v);
            __nv_bfloat16 l = __float2bfloat16(v - __bfloat162float(h));
            __nv_bfloat16* W = (__nv_bfloat16*)g_wcatT;
            W[(size_t)n * KQ +        k] = h;
            W[(size_t)n * KQ +  512 + k] = l;
            W[(size_t)n * KQ + 1024 + k] = h;
        } else {
            int j = idx - 131072;          // < 32768
            int k = j >> 9, n = j & 511;
            float v = Wo[(size_t)k * 512 + n];
            __nv_bfloat16 h = __float2bfloat16(v);
            __nv_bfloat16 l = __float2bfloat16(v - __bfloat162float(h));
            __nv_bfloat16* W = (__nv_bfloat16*)g_woT;
            W[(size_t)n * KO +       k] = h;
            W[(size_t)n * KO +  64 + k] = l;
            W[(size_t)n * KO + 128 + k] = h;
        }
    }
}

// ---------------------------------------------------------------------------
// K2: qkvg GEMM. grid (2 ntiles, 64 mtiles). ntile0 -> bid, ntile1 -> v|g.
// ---------------------------------------------------------------------------
__global__ void __launch_bounds__(256) gemm_qkvg_mma() {
    extern __shared__ __align__(1024) char smem[];
    uint32_t sb = smem_u32(smem);
    int tid = threadIdx.x, wid = tid >> 5, lane = tid & 31;
    int ntile = blockIdx.x, mtile = blockIdx.y;

    const __nv_bfloat16* B = ((const __nv_bfloat16*)g_wcatT) + (size_t)ntile * 128 * KQ;
    size_t aoff = (size_t)mtile * 128 * 512;
    auto getA = [&](int kc) -> const __nv_bfloat16* {
        const __nv_bfloat16* base = (kc < 16) ? (const __nv_bfloat16*)g_xhi
                                              : (const __nv_bfloat16*)g_xlo;
        int kk = (kc < 8) ? kc : ((kc < 16) ? kc - 8 : kc - 16);
        return base + aoff + kk * 64;
    };

    float acc[4][4][4] = {};
    run_mainloop(getA, B, 512, KQ, 24, sb, acc);

    int wm = (wid & 1) * 64, wn = (wid >> 1) * 32;
    int er = lane >> 2, ec = (lane & 3) * 2;
    int m0 = mtile * 128;

    if (ntile == 0) {
        __syncthreads();                   // all warps done with stage smem
        float* S = (float*)smem;           // 128x128 fp32, xor-swizzled cols
        int xm = er << 4;
        #pragma unroll
        for (int mf = 0; mf < 4; mf++)
            #pragma unroll
            for (int nf = 0; nf < 4; nf++) {
                int r = wm + mf * 16 + er;
                int c = (wn + nf * 8 + ec) ^ xm;
                *(float2*)&S[r * 128 + c]       = make_float2(acc[mf][nf][0], acc[mf][nf][1]);
                *(float2*)&S[(r + 8) * 128 + c] = make_float2(acc[mf][nf][2], acc[mf][nf][3]);
            }
        __syncthreads();
        #pragma unroll
        for (int it = 0; it < 2; it++) {
            int item = tid * 2 + it;       // (m, h)
            int m = item >> 2, h = item & 3;
            int x = (m & 7) << 4;
            const float* q = &S[m * 128 + ((h * 16) ^ x)];
            const float* k = &S[m * 128 + ((64 + h * 16) ^ x)];
            float s = 0.f;
            #pragma unroll
            for (int i = 0; i < 16; i++) s += q[i] * k[i];
            g_bid[(size_t)h * M_ROWS + m0 + m] = s * 0.25f;
        }
    } else {
        #pragma unroll
        for (int mf = 0; mf < 4; mf++)
            #pragma unroll
            for (int nf = 0; nf < 4; nf++) {
                int r = m0 + wm + mf * 16 + er;
                int c = wn + nf * 8 + ec;
                *(float2*)&g_vg[(size_t)r * 128 + c]       = make_float2(acc[mf][nf][0], acc[mf][nf][1]);
                *(float2*)&g_vg[(size_t)(r + 8) * 128 + c] = make_float2(acc[mf][nf][2], acc[mf][nf][3]);
            }
    }
}

// ---------------------------------------------------------------------------
// Scan: 512 chunks (16 bh x 32 chunks of 64 steps), 1 warp per chunk.
// ---------------------------------------------------------------------------
#define WSHFL_STATE(om, od, on, off)                                        \
    do {                                                                    \
        om = __shfl_up_sync(0xffffffffu, m, off);                           \
        od = __shfl_up_sync(0xffffffffu, d, off);                           \
        _Pragma("unroll")                                                   \
        for (int _i = 0; _i < 16; _i++)                                     \
            on[_i] = __shfl_up_sync(0xffffffffu, n[_i], off);               \
    } while (0)

// S1: per-chunk local scan; stores p, per-lane inclusive states, chunk sumA
__global__ void __launch_bounds__(128) scan_part1() {
    int warp = threadIdx.x >> 5, lane = threadIdx.x & 31;
    int chunk = blockIdx.x * 4 + warp;
    int bh = chunk >> 5, c = chunk & 31;
    int b = bh >> 2, h = bh & 3;
    int row = b * TT + c * 64 + lane * 2;
    int gl = chunk * 32 + lane;

    const float* A   = g_a   + (size_t)h * M_ROWS;
    const float* BID = g_bid + (size_t)h * M_ROWS;
    float a0 = A[row], a1 = A[row + 1];
    float la = a0 + a1;
    float incl = la;
    #pragma unroll
    for (int off = 1; off < 32; off <<= 1) {
        float o = __shfl_up_sync(0xffffffffu, incl, off);
        if (lane >= off) incl += o;
    }
    float exc = incl - la;
    float p0 = BID[row]     - (exc + a0);
    float p1 = BID[row + 1] - (exc + a0 + a1);

    float m = MSENT, d = 0.f, n[16];
    #pragma unroll
    for (int i = 0; i < 16; i++) n[i] = 0.f;
    sm_step(m, d, n, p0, &g_vg[(size_t)row * 128 + h * 16]);
    sm_step(m, d, n, p1, &g_vg[(size_t)(row + 1) * 128 + h * 16]);

    #pragma unroll
    for (int off = 1; off < 32; off <<= 1) {
        float om, od, on[16];
        WSHFL_STATE(om, od, on, off);
        if (lane >= off) sm_comb(m, d, n, om, od, on);
    }

    g_p0[gl] = p0; g_p1[gl] = p1;
    g_sm[gl] = m;  g_sd[gl] = d;
    #pragma unroll
    for (int i = 0; i < 16; i++) g_sn[i][gl] = n[i];
    if (lane == 31) g_aggA[chunk] = incl;
}

// S2: cross-chunk prefix + replay + gate + z split
__global__ void __launch_bounds__(128) scan_part2(const float* __restrict__ bg) {
    int warp = threadIdx.x >> 5, lane = threadIdx.x & 31;
    int chunk = blockIdx.x * 4 + warp;
    int bh = chunk >> 5, c = chunk & 31;
    int b = bh >> 2, h = bh & 3;
    int row = b * TT + c * 64 + lane * 2;
    int gl = chunk * 32 + lane;

    // --- cross-chunk exclusive prefix (lane l = chunk l of this bh) ---
    float Pm, Pd, Pn[16];
    {
        int cch = bh * 32 + lane;
        float sA = g_aggA[cch];
        int gtop = cch * 32 + 31;
        float m = g_sm[gtop], d = g_sd[gtop], n[16];
        #pragma unroll
        for (int i = 0; i < 16; i++) n[i] = g_sn[i][gtop];

        float cum = sA;
        #pragma unroll
        for (int off = 1; off < 32; off <<= 1) {
            float o = __shfl_up_sync(0xffffffffu, cum, off);
            if (lane >= off) cum += o;
        }
        m -= (cum - sA);                 // -> global frame
        #pragma unroll
        for (int off = 1; off < 32; off <<= 1) {
            float om, od, on[16];
            WSHFL_STATE(om, od, on, off);
            if (lane >= off) sm_comb(m, d, n, om, od, on);
        }
        int src = (c == 0) ? 0 : (c - 1);
        Pm = __shfl_sync(0xffffffffu, m, src);
        Pd = __shfl_sync(0xffffffffu, d, src);
        #pragma unroll
        for (int i = 0; i < 16; i++) Pn[i] = __shfl_sync(0xffffffffu, n[i], src);
        float prefA = __shfl_sync(0xffffffffu, cum, src);
        if (c == 0) {
            Pm = MSENT; Pd = 0.f; prefA = 0.f;
            #pragma unroll
            for (int i = 0; i < 16; i++) Pn[i] = 0.f;
        }
        Pm += prefA;                     // -> this chunk's local frame
    }

    // --- per-lane exclusive state from stored inclusive states ---
    float im = g_sm[gl], id = g_sd[gl], in_[16];
    #pragma unroll
    for (int i = 0; i < 16; i++) in_[i] = g_sn[i][gl];
    float em = __shfl_up_sync(0xffffffffu, im, 1);
    float ed = __shfl_up_sync(0xffffffffu, id, 1);
    float en[16];
    #pragma unroll
    for (int i = 0; i < 16; i++) en[i] = __shfl_up_sync(0xffffffffu, in_[i], 1);
    if (lane == 0) {
        em = MSENT; ed = 0.f;
        #pragma unroll
        for (int i = 0; i < 16; i++) en[i] = 0.f;
    }
    sm_comb(em, ed, en, Pm, Pd, Pn);

    float bgv[16];
    #pragma unroll
    for (int i = 0; i < 16; i++) bgv[i] = bg[h * 16 + i];

    float ps[2] = {g_p0[gl], g_p1[gl]};
    #pragma unroll
    for (int j = 0; j < 2; j++) {
        int r = row + j;
        sm_step(em, ed, en, ps[j], &g_vg[(size_t)r * 128 + h * 16]);
        float inv = __fdividef(1.f, ed);

        const float* gp = &g_vg[(size_t)r * 128 + 64 + h * 16];
        float4 g0 = *(const float4*)&gp[0],  g1 = *(const float4*)&gp[4];
        float4 g2 = *(const float4*)&gp[8],  g3 = *(const float4*)&gp[12];
        float gl16[16] = {g0.x,g0.y,g0.z,g0.w, g1.x,g1.y,g1.z,g1.w,
                          g2.x,g2.y,g2.z,g2.w, g3.x,g3.y,g3.z,g3.w};
        float out[16];
        #pragma unroll
        for (int i = 0; i < 16; i++) {
            float gate = __fdividef(1.f, 1.f + __expf(-(gl16[i] + bgv[i])));
            out[i] = en[i] * inv * gate;
        }
        uint32_t hi[8], lo[8];
        #pragma unroll
        for (int i = 0; i < 8; i++) split2(out[2*i], out[2*i+1], hi[i], lo[i]);
        size_t zb = (size_t)r * 8 + h * 2;
        g_zhi[zb + 0] = make_uint4(hi[0], hi[1], hi[2], hi[3]);
        g_zhi[zb + 1] = make_uint4(hi[4], hi[5], hi[6], hi[7]);
        g_zlo[zb + 0] = make_uint4(lo[0], lo[1], lo[2], lo[3]);
        g_zlo[zb + 1] = make_uint4(lo[4], lo[5], lo[6], lo[7]);
    }
}

// ---------------------------------------------------------------------------
// K4: out = z @ Wo. grid (4 ntiles, 64 mtiles), K'=192 (3 chunks: hi, hi, lo).
// ---------------------------------------------------------------------------
__global__ void __launch_bounds__(256) gemm_out_mma(float* __restrict__ O) {
    extern __shared__ __align__(1024) char smem[];
    uint32_t sb = smem_u32(smem);
    int tid = threadIdx.x, wid = tid >> 5, lane = tid & 31;
    int ntile = blockIdx.x, mtile = blockIdx.y;

    const __nv_bfloat16* B = ((const __nv_bfloat16*)g_woT) + (size_t)ntile * 128 * KO;
    size_t aoff = (size_t)mtile * 128 * 64;
    auto getA = [&](int kc) -> const __nv_bfloat16* {
        return ((kc < 2) ? (const __nv_bfloat16*)g_zhi
                         : (const __nv_bfloat16*)g_zlo) + aoff;
    };

    float acc[4][4][4] = {};
    run_mainloop(getA, B, 64, KO, 3, sb, acc);

    int wm = (wid & 1) * 64, wn = (wid >> 1) * 32;
    int er = lane >> 2, ec = (lane & 3) * 2;
    int m0 = mtile * 128, n0 = ntile * 128;

    #pragma unroll
    for (int mf = 0; mf < 4; mf++)
        #pragma unroll
        for (int nf = 0; nf < 4; nf++) {
            int r = m0 + wm + mf * 16 + er;
            int c = n0 + wn + nf * 8 + ec;
            *(float2*)&O[(size_t)r * 512 + c]       = make_float2(acc[mf][nf][0], acc[mf][nf][1]);
            *(float2*)&O[(size_t)(r + 8) * 512 + c] = make_float2(acc[mf][nf][2], acc[mf][nf][3]);
        }
}

// ---------------------------------------------------------------------------
extern "C" void kernel_launch(void* const* d_in, const int* in_sizes, int n_in,
                              void* d_out, int out_size) {
    const float* x  = (const float*)d_in[0];
    const float* Wq = (const float*)d_in[1];
    const float* Wk = (const float*)d_in[2];
    const float* Wv = (const float*)d_in[3];
    const float* Wa = (const float*)d_in[4];
    const float* ba = (const float*)d_in[5];
    const float* Wg = (const float*)d_in[6];
    const float* bg = (const float*)d_in[7];
    const float* Wo = (const float*)d_in[8];
    float* out = (float*)d_out;

    cudaFuncSetAttribute(gemm_qkvg_mma, cudaFuncAttributeMaxDynamicSharedMemorySize, 98304);
    cudaFuncSetAttribute(gemm_out_mma,  cudaFuncAttributeMaxDynamicSharedMemorySize, 98304);

    setup_kernel<<<1664, 256>>>(x, Wa, ba, Wq, Wk, Wv, Wg, Wo);
    gemm_qkvg_mma<<<dim3(2, 64), 256, 98304>>>();
    scan_part1<<<128, 128>>>();
    scan_part2<<<128, 128>>>(bg);
    gemm_out_mma<<<dim3(4, 64), 256, 98304>>>(out);
}